// round 2
// baseline (speedup 1.0000x reference)
#include <cuda_runtime.h>
#include <math.h>
#include <stdint.h>

// ---------------------------------------------------------------------------
// PhysicsGraphFusion: B=1024 graphs, N=7 nodes, D=1024 dim.
// Outputs packed into d_out (float32):
//   fused   [B,D]      @ 0
//   updated [B,N,D]    @ B*D
//   imp     [B,N]      @ B*D + B*N*D
//   attn    [B,N,N]    @ ... + B*N
//   phys    scalar
//   align   scalar
// ---------------------------------------------------------------------------

#define BB   1024
#define NN   7
#define DD   1024
#define MM   (BB*NN)          // 7168

static const size_t OFF_FUSED = 0;
static const size_t OFF_UPD   = (size_t)BB*DD;                 // 1048576
static const size_t OFF_IMP   = OFF_UPD + (size_t)MM*DD;       // 8388608
static const size_t OFF_ATTN  = OFF_IMP + (size_t)MM;          // 8395776
static const size_t OFF_PHYS  = OFF_ATTN + (size_t)BB*NN*NN;   // 8445952
static const size_t OFF_ALIGN = OFF_PHYS + 1;                  // 8445953

// ---------------- device scratch (static; no runtime allocation) -----------
__device__ float g_q  [ (size_t)MM*DD ];
__device__ float g_k  [ (size_t)MM*DD ];
__device__ float g_v  [ (size_t)MM*DD ];
__device__ float g_la [ (size_t)MM*DD ];
__device__ float g_rb [ (size_t)MM*DD ];
__device__ float g_cc [ (size_t)BB*DD ];
__device__ float g_msg[ (size_t)MM*DD ];
__device__ float g_cat[ (size_t)MM*2*DD ];
__device__ float g_hid[ (size_t)MM*DD ];
__device__ float g_implog[ MM ];
__device__ float g_phys_part [ BB ];
__device__ float g_align_part[ BB ];

__constant__ float c_adj[49] = {
    1,1,0,0,1,1,1,
    1,1,1,1,1,1,1,
    0,1,1,0,1,0,1,
    0,1,0,1,1,1,1,
    1,1,1,1,1,1,1,
    1,1,0,1,1,1,1,
    1,1,1,1,1,1,1 };

__device__ __forceinline__ float geluf(float x) {
    return 0.5f * x * (1.0f + erff(x * 0.70710678118654752440f));
}

// ---------------------------------------------------------------------------
// SGEMM: C[M,Nc] = epilogue(A[M,K] @ W[K,Nc] + bias)
// BM=BN=128, BK=8, 256 threads, 8x8 per thread. M%128==0, Nc%128==0, K%8==0.
// ---------------------------------------------------------------------------
__global__ __launch_bounds__(256, 2)
void sgemm_kernel(int M, int Nc, int K,
                  const float* __restrict__ A, int lda,
                  const float* __restrict__ W,
                  const float* __restrict__ bias,
                  const float* __restrict__ resid,
                  float* __restrict__ C,
                  int applyGelu)
{
    const int BM = 128, BN = 128, BK = 8;
    __shared__ float As[BK][BM];
    __shared__ float Bs[BK][BN];

    const int tid  = threadIdx.x;
    const int tx   = tid & 15;       // 0..15 -> col groups of 8
    const int ty   = tid >> 4;       // 0..15 -> row groups of 8
    const int brow = blockIdx.y;
    const int bcol = blockIdx.x;

    // A tile loader: 128x8, one float4 per thread
    const int aRow = tid >> 1;           // 0..127
    const int aCol = (tid & 1) * 4;      // 0 or 4
    // W tile loader: 8x128, one float4 per thread
    const int bRow = tid >> 5;           // 0..7
    const int bCol = (tid & 31) * 4;     // 0..124

    const float* Aptr = A + (size_t)(brow * BM) * lda;
    const float* Wptr = W + bcol * BN;

    float acc[8][8];
    #pragma unroll
    for (int i = 0; i < 8; i++)
        #pragma unroll
        for (int j = 0; j < 8; j++) acc[i][j] = 0.0f;

    for (int k0 = 0; k0 < K; k0 += BK) {
        float4 a4 = *(const float4*)(Aptr + (size_t)aRow * lda + k0 + aCol);
        As[aCol + 0][aRow] = a4.x;
        As[aCol + 1][aRow] = a4.y;
        As[aCol + 2][aRow] = a4.z;
        As[aCol + 3][aRow] = a4.w;
        float4 b4 = *(const float4*)(Wptr + (size_t)(k0 + bRow) * Nc + bCol);
        *(float4*)&Bs[bRow][bCol] = b4;
        __syncthreads();

        #pragma unroll
        for (int kk = 0; kk < BK; kk++) {
            float aReg[8], bReg[8];
            #pragma unroll
            for (int i = 0; i < 8; i++) aReg[i] = As[kk][ty * 8 + i];
            #pragma unroll
            for (int j = 0; j < 8; j++) bReg[j] = Bs[kk][tx * 8 + j];
            #pragma unroll
            for (int i = 0; i < 8; i++)
                #pragma unroll
                for (int j = 0; j < 8; j++)
                    acc[i][j] = fmaf(aReg[i], bReg[j], acc[i][j]);
        }
        __syncthreads();
    }

    // epilogue
    #pragma unroll
    for (int i = 0; i < 8; i++) {
        int row = brow * BM + ty * 8 + i;
        size_t base = (size_t)row * Nc + bcol * BN + tx * 8;
        #pragma unroll
        for (int j = 0; j < 8; j++) {
            int col = bcol * BN + tx * 8 + j;
            float v = acc[i][j];
            if (bias)  v += bias[col];
            if (applyGelu) v = geluf(v);
            if (resid) v += resid[base + j];
            C[base + j] = v;
        }
    }
}

// ---------------------------------------------------------------------------
// Per-batch attention: edge-MLP logits + q.k logits + mask + softmax + messages
// grid = B, block = 256 (8 warps)
// ---------------------------------------------------------------------------
__global__ __launch_bounds__(256)
void attn_kernel(const float* __restrict__ be1,
                 const float* __restrict__ We2,
                 const float* __restrict__ be2,
                 float* __restrict__ out_attn)
{
    const int b    = blockIdx.x;
    const int tid  = threadIdx.x;
    const int lane = tid & 31;
    const int wid  = tid >> 5;

    __shared__ float s_logit[49];
    __shared__ float s_attn[49];

    const float* q  = g_q  + (size_t)b * NN * DD;
    const float* k  = g_k  + (size_t)b * NN * DD;
    const float* la = g_la + (size_t)b * NN * DD;
    const float* rb = g_rb + (size_t)b * NN * DD;
    const float* cc = g_cc + (size_t)b * DD;

    for (int p = wid; p < 49; p += 8) {
        const int n = p / 7, m = p % 7;
        const float* qn  = q  + n * DD;
        const float* km  = k  + m * DD;
        const float* lan = la + n * DD;
        const float* rbm = rb + m * DD;
        float qk = 0.0f, e = 0.0f;
        for (int d = lane; d < DD; d += 32) {
            qk = fmaf(qn[d], km[d], qk);
            float h = lan[d] + rbm[d] + cc[d] + be1[d];
            e  = fmaf(geluf(h), We2[d], e);
        }
        #pragma unroll
        for (int o = 16; o > 0; o >>= 1) {
            qk += __shfl_down_sync(0xffffffffu, qk, o);
            e  += __shfl_down_sync(0xffffffffu, e,  o);
        }
        if (lane == 0)
            s_logit[p] = qk * (1.0f / 32.0f) + e + be2[0]
                       + (c_adj[p] - 1.0f) * 10000.0f;
    }
    __syncthreads();

    if (tid < 7) {
        const int n = tid;
        float mx = -1e30f;
        #pragma unroll
        for (int m = 0; m < 7; m++) mx = fmaxf(mx, s_logit[n * 7 + m]);
        float ex[7], s = 0.0f;
        #pragma unroll
        for (int m = 0; m < 7; m++) { ex[m] = expf(s_logit[n * 7 + m] - mx); s += ex[m]; }
        #pragma unroll
        for (int m = 0; m < 7; m++) {
            float a = ex[m] / s;
            s_attn[n * 7 + m] = a;
            out_attn[(size_t)b * 49 + n * 7 + m] = a;
        }
    }
    __syncthreads();

    const float* v   = g_v   + (size_t)b * NN * DD;
    float*       msg = g_msg + (size_t)b * NN * DD;
    for (int d = tid; d < DD; d += 256) {
        float vv[7];
        #pragma unroll
        for (int m = 0; m < 7; m++) vv[m] = v[m * DD + d];
        #pragma unroll
        for (int n = 0; n < 7; n++) {
            float acc = 0.0f;
            #pragma unroll
            for (int m = 0; m < 7; m++) acc = fmaf(s_attn[n * 7 + m], vv[m], acc);
            msg[n * DD + d] = acc;
        }
    }
}

// g_cat = [nodes | g_msg]
__global__ void concat_nm_kernel(const float* __restrict__ nodes)
{
    size_t i = (size_t)blockIdx.x * blockDim.x + threadIdx.x;
    if (i >= (size_t)MM * DD) return;
    size_t row = i / DD, d = i % DD;
    g_cat[row * 2 * DD + d]      = nodes[i];
    g_cat[row * 2 * DD + DD + d] = g_msg[i];
}

// g_cat = [updated | updated[b, N-1] broadcast]
__global__ void concat_ug_kernel(const float* __restrict__ upd)
{
    size_t i = (size_t)blockIdx.x * blockDim.x + threadIdx.x;
    if (i >= (size_t)MM * DD) return;
    size_t row = i / DD, d = i % DD;
    size_t b = row / NN;
    g_cat[row * 2 * DD + d]      = upd[i];
    g_cat[row * 2 * DD + DD + d] = upd[(b * NN + (NN - 1)) * (size_t)DD + d];
}

// imp_logits = g_hid @ Wi2 + bi2     (grid = MM rows, 128 threads)
__global__ __launch_bounds__(128)
void gemv_imp_kernel(const float* __restrict__ Wi2, const float* __restrict__ bi2)
{
    const int row = blockIdx.x;
    const int tid = threadIdx.x;
    const float* h = g_hid + (size_t)row * DD;
    float s = 0.0f;
    for (int d = tid; d < DD; d += 128) s = fmaf(h[d], Wi2[d], s);
    #pragma unroll
    for (int o = 16; o > 0; o >>= 1) s += __shfl_down_sync(0xffffffffu, s, o);
    __shared__ float red[4];
    if ((tid & 31) == 0) red[tid >> 5] = s;
    __syncthreads();
    if (tid == 0)
        g_implog[row] = red[0] + red[1] + red[2] + red[3] + bi2[0];
}

// softmax over N + _cap_importance; grid = B, 32 threads (lane 0 works)
__global__ void imp_kernel(float* __restrict__ out_imp)
{
    const int b = blockIdx.x;
    if (threadIdx.x != 0) return;
    float l[7], mx = -1e30f;
    #pragma unroll
    for (int n = 0; n < 7; n++) { l[n] = g_implog[b * 7 + n]; mx = fmaxf(mx, l[n]); }
    float s = 0.0f;
    #pragma unroll
    for (int n = 0; n < 7; n++) { l[n] = expf(l[n] - mx); s += l[n]; }
    float imp[7];
    #pragma unroll
    for (int n = 0; n < 7; n++) imp[n] = l[n] / s;

    const float cap[7] = {1.f,1.f,1.f,0.26f,1.f,1.f,0.24f};
    const float fr [7] = {1.f,1.f,1.f,0.f,  1.f,1.f,0.f };
    float capped[7], sc = 0.0f, fm = 0.0f;
    #pragma unroll
    for (int n = 0; n < 7; n++) {
        capped[n] = fminf(imp[n], cap[n]);
        sc += capped[n];
        fm += imp[n] * fr[n];
    }
    float residual = fmaxf(1.0f - sc, 0.0f);
    float redis[7], sr = 0.0f;
    #pragma unroll
    for (int n = 0; n < 7; n++) {
        float fs = (fm > 1e-6f) ? imp[n] * fr[n] / fmaxf(fm, 1e-6f) : fr[n] / 5.0f;
        redis[n] = capped[n] + fs * residual;
        sr += redis[n];
    }
    #pragma unroll
    for (int n = 0; n < 7; n++)
        out_imp[b * 7 + n] = redis[n] / fmaxf(sr, 1e-6f);
}

// fused[b,d] = sum_n imp[b,n] * updated[b,n,d]; grid = B, 256 threads
__global__ __launch_bounds__(256)
void fused_kernel(const float* __restrict__ out_imp,
                  const float* __restrict__ upd,
                  float* __restrict__ out_fused)
{
    const int b = blockIdx.x;
    const int tid = threadIdx.x;
    __shared__ float w[7];
    if (tid < 7) w[tid] = out_imp[b * 7 + tid];
    __syncthreads();
    const float* u = upd + (size_t)b * NN * DD;
    for (int d = tid; d < DD; d += 256) {
        float acc = 0.0f;
        #pragma unroll
        for (int n = 0; n < 7; n++) acc = fmaf(w[n], u[n * DD + d], acc);
        out_fused[(size_t)b * DD + d] = acc;
    }
}

// physics + alignment partials per batch; grid = B, 256 threads (8 warps)
__global__ __launch_bounds__(256)
void physalign_kernel(const float* __restrict__ upd,
                      const float* __restrict__ fused)
{
    const int b = blockIdx.x;
    const int tid = threadIdx.x;
    const int lane = tid & 31, wid = tid >> 5;
    __shared__ float dots[57];
    const float* u = upd   + (size_t)b * NN * DD;
    const float* f = fused + (size_t)b * DD;

    for (int t = wid; t < 57; t += 8) {
        const float *x, *y;
        if (t < 49)      { x = u + (t / 7) * DD; y = u + (t % 7) * DD; }
        else if (t < 56) { x = u + (t - 49) * DD; y = f; }
        else             { x = f; y = f; }
        float s = 0.0f;
        for (int d = lane; d < DD; d += 32) s = fmaf(x[d], y[d], s);
        #pragma unroll
        for (int o = 16; o > 0; o >>= 1) s += __shfl_down_sync(0xffffffffu, s, o);
        if (lane == 0) dots[t] = s;
    }
    __syncthreads();

    if (tid == 0) {
        float norms[7];
        #pragma unroll
        for (int n = 0; n < 7; n++) norms[n] = sqrtf(dots[n * 7 + n]);
        float edge = 0.0f, non = 0.0f;
        #pragma unroll
        for (int n = 0; n < 7; n++) {
            #pragma unroll
            for (int m = 0; m < 7; m++) {
                float cs = dots[n * 7 + m] / fmaxf(norms[n] * norms[m], 1e-8f);
                float a = c_adj[n * 7 + m];
                edge += (1.0f - cs) * a;
                float nonmask = (1.0f - a) * ((n == m) ? 0.0f : 1.0f);
                non += fmaxf(cs - 0.35f, 0.0f) * nonmask;
            }
        }
        g_phys_part[b] = edge / 41.0f + 0.5f * non / 8.0f;

        float fn = sqrtf(dots[56]);
        float al = 0.0f;
        #pragma unroll
        for (int n = 0; n < 7; n++) {
            float cs = dots[49 + n] / (fmaxf(norms[n], 1e-12f) * fmaxf(fn, 1e-12f));
            al += 1.0f - cs;
        }
        g_align_part[b] = al;
    }
}

// deterministic final reduction -> scalars
__global__ __launch_bounds__(256)
void final_reduce_kernel(float* __restrict__ out)
{
    const int tid = threadIdx.x;
    float p = 0.0f, a = 0.0f;
    for (int b = tid; b < BB; b += 256) { p += g_phys_part[b]; a += g_align_part[b]; }
    __shared__ float sp[256], sa[256];
    sp[tid] = p; sa[tid] = a;
    __syncthreads();
    for (int s = 128; s > 0; s >>= 1) {
        if (tid < s) { sp[tid] += sp[tid + s]; sa[tid] += sa[tid + s]; }
        __syncthreads();
    }
    if (tid == 0) {
        out[OFF_PHYS]  = sp[0];
        out[OFF_ALIGN] = sa[0] / (float)(BB * NN);
    }
}

// ---------------------------------------------------------------------------
extern "C" void kernel_launch(void* const* d_in, const int* in_sizes, int n_in,
                              void* d_out, int out_size)
{
    const float* nodes = (const float*)d_in[0];
    const float* Wq    = (const float*)d_in[1];
    const float* bq    = (const float*)d_in[2];
    const float* Wk    = (const float*)d_in[3];
    const float* bk    = (const float*)d_in[4];
    const float* Wv    = (const float*)d_in[5];
    const float* bv    = (const float*)d_in[6];
    const float* We1   = (const float*)d_in[7];
    const float* be1   = (const float*)d_in[8];
    const float* We2   = (const float*)d_in[9];
    const float* be2   = (const float*)d_in[10];
    const float* Wu1   = (const float*)d_in[11];
    const float* bu1   = (const float*)d_in[12];
    const float* Wu2   = (const float*)d_in[13];
    const float* bu2   = (const float*)d_in[14];
    const float* Wi1   = (const float*)d_in[15];
    const float* bi1   = (const float*)d_in[16];
    const float* Wi2   = (const float*)d_in[17];
    const float* bi2   = (const float*)d_in[18];

    float* out       = (float*)d_out;
    float* out_fused = out + OFF_FUSED;
    float* out_upd   = out + OFF_UPD;
    float* out_imp   = out + OFF_IMP;
    float* out_attn  = out + OFF_ATTN;

    float* q   = nullptr; cudaGetSymbolAddress((void**)&q,   g_q);
    float* k   = nullptr; cudaGetSymbolAddress((void**)&k,   g_k);
    float* v   = nullptr; cudaGetSymbolAddress((void**)&v,   g_v);
    float* la  = nullptr; cudaGetSymbolAddress((void**)&la,  g_la);
    float* rb  = nullptr; cudaGetSymbolAddress((void**)&rb,  g_rb);
    float* cc  = nullptr; cudaGetSymbolAddress((void**)&cc,  g_cc);
    float* cat = nullptr; cudaGetSymbolAddress((void**)&cat, g_cat);
    float* hid = nullptr; cudaGetSymbolAddress((void**)&hid, g_hid);

    dim3 blk(256);
    dim3 grid_big(DD / 128, MM / 128);   // 8 x 56
    dim3 grid_cc (DD / 128, BB / 128);   // 8 x 8

    // projections
    sgemm_kernel<<<grid_big, blk>>>(MM, DD, DD, nodes, DD, Wq, bq, nullptr, q, 0);
    sgemm_kernel<<<grid_big, blk>>>(MM, DD, DD, nodes, DD, Wk, bk, nullptr, k, 0);
    sgemm_kernel<<<grid_big, blk>>>(MM, DD, DD, nodes, DD, Wv, bv, nullptr, v, 0);
    sgemm_kernel<<<grid_big, blk>>>(MM, DD, DD, nodes, DD, We1,             nullptr, nullptr, la, 0);
    sgemm_kernel<<<grid_big, blk>>>(MM, DD, DD, nodes, DD, We1 + (size_t)DD * DD,     nullptr, nullptr, rb, 0);
    sgemm_kernel<<<grid_cc,  blk>>>(BB, DD, DD, nodes + (size_t)(NN - 1) * DD, NN * DD,
                                    We1 + (size_t)2 * DD * DD, nullptr, nullptr, cc, 0);

    // edge MLP + attention + messages
    attn_kernel<<<BB, blk>>>(be1, We2, be2, out_attn);

    // update MLP
    int nconcat = (int)(((size_t)MM * DD + 255) / 256);
    concat_nm_kernel<<<nconcat, blk>>>(nodes);
    sgemm_kernel<<<grid_big, blk>>>(MM, DD, 2 * DD, cat, 2 * DD, Wu1, bu1, nullptr, hid, 1);
    sgemm_kernel<<<grid_big, blk>>>(MM, DD, DD, hid, DD, Wu2, bu2, nodes, out_upd, 0);

    // importance MLP
    concat_ug_kernel<<<nconcat, blk>>>(out_upd);
    sgemm_kernel<<<grid_big, blk>>>(MM, DD, 2 * DD, cat, 2 * DD, Wi1, bi1, nullptr, hid, 1);
    gemv_imp_kernel<<<MM, 128>>>(Wi2, bi2);
    imp_kernel<<<BB, 32>>>(out_imp);

    // fused output + losses
    fused_kernel<<<BB, blk>>>(out_imp, out_upd, out_fused);
    physalign_kernel<<<BB, blk>>>(out_upd, out_fused);
    final_reduce_kernel<<<1, blk>>>(out);
}

// round 3
// speedup vs baseline: 1.4420x; 1.4420x over previous
#include <cuda_runtime.h>
#include <math.h>
#include <stdint.h>

// ---------------------------------------------------------------------------
// PhysicsGraphFusion: B=1024 graphs, N=7 nodes, D=1024 dim.
// Round 2: all GEMMs on tensor cores via 3xTF32 mma.sync (m16n8k8).
// ---------------------------------------------------------------------------

#define BB   1024
#define NN   7
#define DD   1024
#define MM   (BB*NN)          // 7168

static const size_t OFF_FUSED = 0;
static const size_t OFF_UPD   = (size_t)BB*DD;
static const size_t OFF_IMP   = OFF_UPD + (size_t)MM*DD;
static const size_t OFF_ATTN  = OFF_IMP + (size_t)MM;
static const size_t OFF_PHYS  = OFF_ATTN + (size_t)BB*NN*NN;
static const size_t OFF_ALIGN = OFF_PHYS + 1;

// ---------------- device scratch (static; no runtime allocation) -----------
__device__ float g_q  [ (size_t)MM*DD ];
__device__ float g_k  [ (size_t)MM*DD ];
__device__ float g_v  [ (size_t)MM*DD ];
__device__ float g_la [ (size_t)MM*DD ];
__device__ float g_rb [ (size_t)MM*DD ];
__device__ float g_cc [ (size_t)BB*DD ];
__device__ float g_msg[ (size_t)MM*DD ];
__device__ float g_cat[ (size_t)MM*2*DD ];
__device__ float g_hid[ (size_t)MM*DD ];
__device__ float g_implog[ MM ];
__device__ float g_phys_part [ BB ];
__device__ float g_align_part[ BB ];

__constant__ float c_adj[49] = {
    1,1,0,0,1,1,1,
    1,1,1,1,1,1,1,
    0,1,1,0,1,0,1,
    0,1,0,1,1,1,1,
    1,1,1,1,1,1,1,
    1,1,0,1,1,1,1,
    1,1,1,1,1,1,1 };

__device__ __forceinline__ float geluf(float x) {
    return 0.5f * x * (1.0f + erff(x * 0.70710678118654752440f));
}

__device__ __forceinline__ float tf32_rna(float x) {
    float r;
    asm("cvt.rna.tf32.f32 %0, %1;" : "=f"(r) : "f"(x));
    return r;
}

__device__ __forceinline__ void mma_tf32(float* c,
    uint32_t a0, uint32_t a1, uint32_t a2, uint32_t a3,
    uint32_t b0, uint32_t b1)
{
    asm volatile(
        "mma.sync.aligned.m16n8k8.row.col.f32.tf32.tf32.f32 "
        "{%0,%1,%2,%3}, {%4,%5,%6,%7}, {%8,%9}, {%0,%1,%2,%3};\n"
        : "+f"(c[0]), "+f"(c[1]), "+f"(c[2]), "+f"(c[3])
        : "r"(a0), "r"(a1), "r"(a2), "r"(a3), "r"(b0), "r"(b1));
}

// ---------------------------------------------------------------------------
// Tensor-core GEMM: C[M,Nc] = epi(A[M,K] @ W[K,Nc] + bias), 3xTF32.
// BM=BN=128, BK=32, 256 threads (8 warps, 4x2), warp tile 32x64.
// M%128==0, Nc%128==0, K%32==0.
// Shared (dynamic): As_hi/As_lo [128][36], Bs_hi/Bs_lo [32][136].
// ---------------------------------------------------------------------------
#define AS_STRIDE 36
#define BS_STRIDE 136
#define SMEM_GEMM_BYTES ((2*128*AS_STRIDE + 2*32*BS_STRIDE) * 4)

__global__ void gemm_tc_kernel(int M, int Nc, int K,
                               const float* __restrict__ A, int lda,
                               const float* __restrict__ W,
                               const float* __restrict__ bias,
                               const float* __restrict__ resid,
                               float* __restrict__ C,
                               int applyGelu)
{
    extern __shared__ float smem[];
    float* As_h = smem;                         // 128*36
    float* As_l = As_h + 128 * AS_STRIDE;
    float* Bs_h = As_l + 128 * AS_STRIDE;       // 32*136
    float* Bs_l = Bs_h + 32 * BS_STRIDE;

    const int tid  = threadIdx.x;
    const int lane = tid & 31;
    const int wid  = tid >> 5;
    const int wm   = wid & 3;      // 0..3 -> 32-row slices
    const int wn   = wid >> 2;     // 0..1 -> 64-col slices
    const int gid  = lane >> 2;    // 0..7
    const int tig  = lane & 3;     // 0..3

    const int brow = blockIdx.y;
    const int bcol = blockIdx.x;

    const float* Aptr = A + (size_t)(brow * 128) * lda;
    const float* Wptr = W + (size_t)bcol * 128;

    float acc[2][8][4];
    #pragma unroll
    for (int mi = 0; mi < 2; mi++)
        #pragma unroll
        for (int ni = 0; ni < 8; ni++)
            #pragma unroll
            for (int r = 0; r < 4; r++) acc[mi][ni][r] = 0.0f;

    for (int k0 = 0; k0 < K; k0 += 32) {
        // ---- load + split tiles ----
        #pragma unroll
        for (int it = 0; it < 4; it++) {
            int idx  = it * 256 + tid;            // 0..1023 float4 slots
            // A: 128 rows x 8 float4
            int ar   = idx >> 3;
            int ac4  = (idx & 7) * 4;
            float4 a4 = *(const float4*)(Aptr + (size_t)ar * lda + k0 + ac4);
            float h, l;
            h = tf32_rna(a4.x); l = tf32_rna(a4.x - h);
            As_h[ar*AS_STRIDE + ac4 + 0] = h; As_l[ar*AS_STRIDE + ac4 + 0] = l;
            h = tf32_rna(a4.y); l = tf32_rna(a4.y - h);
            As_h[ar*AS_STRIDE + ac4 + 1] = h; As_l[ar*AS_STRIDE + ac4 + 1] = l;
            h = tf32_rna(a4.z); l = tf32_rna(a4.z - h);
            As_h[ar*AS_STRIDE + ac4 + 2] = h; As_l[ar*AS_STRIDE + ac4 + 2] = l;
            h = tf32_rna(a4.w); l = tf32_rna(a4.w - h);
            As_h[ar*AS_STRIDE + ac4 + 3] = h; As_l[ar*AS_STRIDE + ac4 + 3] = l;
            // B: 32 rows x 32 float4
            int br   = idx >> 5;
            int bc4  = (idx & 31) * 4;
            float4 b4 = *(const float4*)(Wptr + (size_t)(k0 + br) * Nc + bc4);
            h = tf32_rna(b4.x); l = tf32_rna(b4.x - h);
            Bs_h[br*BS_STRIDE + bc4 + 0] = h; Bs_l[br*BS_STRIDE + bc4 + 0] = l;
            h = tf32_rna(b4.y); l = tf32_rna(b4.y - h);
            Bs_h[br*BS_STRIDE + bc4 + 1] = h; Bs_l[br*BS_STRIDE + bc4 + 1] = l;
            h = tf32_rna(b4.z); l = tf32_rna(b4.z - h);
            Bs_h[br*BS_STRIDE + bc4 + 2] = h; Bs_l[br*BS_STRIDE + bc4 + 2] = l;
            h = tf32_rna(b4.w); l = tf32_rna(b4.w - h);
            Bs_h[br*BS_STRIDE + bc4 + 3] = h; Bs_l[br*BS_STRIDE + bc4 + 3] = l;
        }
        __syncthreads();

        // ---- compute ----
        #pragma unroll
        for (int kk = 0; kk < 4; kk++) {
            uint32_t ah[2][4], al[2][4];
            #pragma unroll
            for (int mi = 0; mi < 2; mi++) {
                int r0 = (wm * 32 + mi * 16 + gid) * AS_STRIDE + kk * 8 + tig;
                ah[mi][0] = __float_as_uint(As_h[r0]);
                ah[mi][1] = __float_as_uint(As_h[r0 + 8 * AS_STRIDE]);
                ah[mi][2] = __float_as_uint(As_h[r0 + 4]);
                ah[mi][3] = __float_as_uint(As_h[r0 + 8 * AS_STRIDE + 4]);
                al[mi][0] = __float_as_uint(As_l[r0]);
                al[mi][1] = __float_as_uint(As_l[r0 + 8 * AS_STRIDE]);
                al[mi][2] = __float_as_uint(As_l[r0 + 4]);
                al[mi][3] = __float_as_uint(As_l[r0 + 8 * AS_STRIDE + 4]);
            }
            #pragma unroll
            for (int ni = 0; ni < 8; ni++) {
                int bi = (kk * 8 + tig) * BS_STRIDE + wn * 64 + ni * 8 + gid;
                uint32_t bh0 = __float_as_uint(Bs_h[bi]);
                uint32_t bh1 = __float_as_uint(Bs_h[bi + 4 * BS_STRIDE]);
                uint32_t bl0 = __float_as_uint(Bs_l[bi]);
                uint32_t bl1 = __float_as_uint(Bs_l[bi + 4 * BS_STRIDE]);
                #pragma unroll
                for (int mi = 0; mi < 2; mi++) {
                    mma_tf32(acc[mi][ni], ah[mi][0], ah[mi][1], ah[mi][2], ah[mi][3], bh0, bh1);
                    mma_tf32(acc[mi][ni], ah[mi][0], ah[mi][1], ah[mi][2], ah[mi][3], bl0, bl1);
                    mma_tf32(acc[mi][ni], al[mi][0], al[mi][1], al[mi][2], al[mi][3], bh0, bh1);
                }
            }
        }
        __syncthreads();
    }

    // ---- epilogue ----
    #pragma unroll
    for (int mi = 0; mi < 2; mi++) {
        #pragma unroll
        for (int ni = 0; ni < 8; ni++) {
            int row0 = brow * 128 + wm * 32 + mi * 16 + gid;
            int col0 = bcol * 128 + wn * 64 + ni * 8 + tig * 2;
            #pragma unroll
            for (int half = 0; half < 2; half++) {
                int row = row0 + half * 8;
                size_t base = (size_t)row * Nc + col0;
                float v0 = acc[mi][ni][half * 2 + 0];
                float v1 = acc[mi][ni][half * 2 + 1];
                if (bias) { v0 += bias[col0]; v1 += bias[col0 + 1]; }
                if (applyGelu) { v0 = geluf(v0); v1 = geluf(v1); }
                if (resid) { v0 += resid[base]; v1 += resid[base + 1]; }
                C[base]     = v0;
                C[base + 1] = v1;
            }
        }
    }
}

// ---------------------------------------------------------------------------
// Per-batch attention: edge-MLP logits + q.k logits + mask + softmax + messages
// ---------------------------------------------------------------------------
__global__ __launch_bounds__(256)
void attn_kernel(const float* __restrict__ be1,
                 const float* __restrict__ We2,
                 const float* __restrict__ be2,
                 float* __restrict__ out_attn)
{
    const int b    = blockIdx.x;
    const int tid  = threadIdx.x;
    const int lane = tid & 31;
    const int wid  = tid >> 5;

    __shared__ float s_logit[49];
    __shared__ float s_attn[49];

    const float* q  = g_q  + (size_t)b * NN * DD;
    const float* k  = g_k  + (size_t)b * NN * DD;
    const float* la = g_la + (size_t)b * NN * DD;
    const float* rb = g_rb + (size_t)b * NN * DD;
    const float* cc = g_cc + (size_t)b * DD;

    for (int p = wid; p < 49; p += 8) {
        const int n = p / 7, m = p % 7;
        const float* qn  = q  + n * DD;
        const float* km  = k  + m * DD;
        const float* lan = la + n * DD;
        const float* rbm = rb + m * DD;
        float qk = 0.0f, e = 0.0f;
        for (int d = lane; d < DD; d += 32) {
            qk = fmaf(qn[d], km[d], qk);
            float h = lan[d] + rbm[d] + cc[d] + be1[d];
            e  = fmaf(geluf(h), We2[d], e);
        }
        #pragma unroll
        for (int o = 16; o > 0; o >>= 1) {
            qk += __shfl_down_sync(0xffffffffu, qk, o);
            e  += __shfl_down_sync(0xffffffffu, e,  o);
        }
        if (lane == 0)
            s_logit[p] = qk * (1.0f / 32.0f) + e + be2[0]
                       + (c_adj[p] - 1.0f) * 10000.0f;
    }
    __syncthreads();

    if (tid < 7) {
        const int n = tid;
        float mx = -1e30f;
        #pragma unroll
        for (int m = 0; m < 7; m++) mx = fmaxf(mx, s_logit[n * 7 + m]);
        float ex[7], s = 0.0f;
        #pragma unroll
        for (int m = 0; m < 7; m++) { ex[m] = expf(s_logit[n * 7 + m] - mx); s += ex[m]; }
        #pragma unroll
        for (int m = 0; m < 7; m++) {
            float a = ex[m] / s;
            s_attn[n * 7 + m] = a;
            out_attn[(size_t)b * 49 + n * 7 + m] = a;
        }
    }
    __syncthreads();

    const float* v   = g_v   + (size_t)b * NN * DD;
    float*       msg = g_msg + (size_t)b * NN * DD;
    for (int d = tid; d < DD; d += 256) {
        float vv[7];
        #pragma unroll
        for (int m = 0; m < 7; m++) vv[m] = v[m * DD + d];
        #pragma unroll
        for (int n = 0; n < 7; n++) {
            float acc = 0.0f;
            #pragma unroll
            for (int m = 0; m < 7; m++) acc = fmaf(s_attn[n * 7 + m], vv[m], acc);
            msg[n * DD + d] = acc;
        }
    }
}

// g_cat = [nodes | g_msg]
__global__ void concat_nm_kernel(const float* __restrict__ nodes)
{
    size_t i = (size_t)blockIdx.x * blockDim.x + threadIdx.x;
    if (i >= (size_t)MM * DD) return;
    size_t row = i / DD, d = i % DD;
    g_cat[row * 2 * DD + d]      = nodes[i];
    g_cat[row * 2 * DD + DD + d] = g_msg[i];
}

// g_cat = [updated | updated[b, N-1] broadcast]
__global__ void concat_ug_kernel(const float* __restrict__ upd)
{
    size_t i = (size_t)blockIdx.x * blockDim.x + threadIdx.x;
    if (i >= (size_t)MM * DD) return;
    size_t row = i / DD, d = i % DD;
    size_t b = row / NN;
    g_cat[row * 2 * DD + d]      = upd[i];
    g_cat[row * 2 * DD + DD + d] = upd[(b * NN + (NN - 1)) * (size_t)DD + d];
}

// imp_logits = g_hid @ Wi2 + bi2
__global__ __launch_bounds__(128)
void gemv_imp_kernel(const float* __restrict__ Wi2, const float* __restrict__ bi2)
{
    const int row = blockIdx.x;
    const int tid = threadIdx.x;
    const float* h = g_hid + (size_t)row * DD;
    float s = 0.0f;
    for (int d = tid; d < DD; d += 128) s = fmaf(h[d], Wi2[d], s);
    #pragma unroll
    for (int o = 16; o > 0; o >>= 1) s += __shfl_down_sync(0xffffffffu, s, o);
    __shared__ float red[4];
    if ((tid & 31) == 0) red[tid >> 5] = s;
    __syncthreads();
    if (tid == 0)
        g_implog[row] = red[0] + red[1] + red[2] + red[3] + bi2[0];
}

// softmax over N + _cap_importance
__global__ void imp_kernel(float* __restrict__ out_imp)
{
    const int b = blockIdx.x;
    if (threadIdx.x != 0) return;
    float l[7], mx = -1e30f;
    #pragma unroll
    for (int n = 0; n < 7; n++) { l[n] = g_implog[b * 7 + n]; mx = fmaxf(mx, l[n]); }
    float s = 0.0f;
    #pragma unroll
    for (int n = 0; n < 7; n++) { l[n] = expf(l[n] - mx); s += l[n]; }
    float imp[7];
    #pragma unroll
    for (int n = 0; n < 7; n++) imp[n] = l[n] / s;

    const float cap[7] = {1.f,1.f,1.f,0.26f,1.f,1.f,0.24f};
    const float fr [7] = {1.f,1.f,1.f,0.f,  1.f,1.f,0.f };
    float capped[7], sc = 0.0f, fm = 0.0f;
    #pragma unroll
    for (int n = 0; n < 7; n++) {
        capped[n] = fminf(imp[n], cap[n]);
        sc += capped[n];
        fm += imp[n] * fr[n];
    }
    float residual = fmaxf(1.0f - sc, 0.0f);
    float redis[7], sr = 0.0f;
    #pragma unroll
    for (int n = 0; n < 7; n++) {
        float fs = (fm > 1e-6f) ? imp[n] * fr[n] / fmaxf(fm, 1e-6f) : fr[n] / 5.0f;
        redis[n] = capped[n] + fs * residual;
        sr += redis[n];
    }
    #pragma unroll
    for (int n = 0; n < 7; n++)
        out_imp[b * 7 + n] = redis[n] / fmaxf(sr, 1e-6f);
}

// fused[b,d] = sum_n imp[b,n] * updated[b,n,d]
__global__ __launch_bounds__(256)
void fused_kernel(const float* __restrict__ out_imp,
                  const float* __restrict__ upd,
                  float* __restrict__ out_fused)
{
    const int b = blockIdx.x;
    const int tid = threadIdx.x;
    __shared__ float w[7];
    if (tid < 7) w[tid] = out_imp[b * 7 + tid];
    __syncthreads();
    const float* u = upd + (size_t)b * NN * DD;
    for (int d = tid; d < DD; d += 256) {
        float acc = 0.0f;
        #pragma unroll
        for (int n = 0; n < 7; n++) acc = fmaf(w[n], u[n * DD + d], acc);
        out_fused[(size_t)b * DD + d] = acc;
    }
}

// physics + alignment partials per batch
__global__ __launch_bounds__(256)
void physalign_kernel(const float* __restrict__ upd,
                      const float* __restrict__ fused)
{
    const int b = blockIdx.x;
    const int tid = threadIdx.x;
    const int lane = tid & 31, wid = tid >> 5;
    __shared__ float dots[57];
    const float* u = upd   + (size_t)b * NN * DD;
    const float* f = fused + (size_t)b * DD;

    for (int t = wid; t < 57; t += 8) {
        const float *x, *y;
        if (t < 49)      { x = u + (t / 7) * DD; y = u + (t % 7) * DD; }
        else if (t < 56) { x = u + (t - 49) * DD; y = f; }
        else             { x = f; y = f; }
        float s = 0.0f;
        for (int d = lane; d < DD; d += 32) s = fmaf(x[d], y[d], s);
        #pragma unroll
        for (int o = 16; o > 0; o >>= 1) s += __shfl_down_sync(0xffffffffu, s, o);
        if (lane == 0) dots[t] = s;
    }
    __syncthreads();

    if (tid == 0) {
        float norms[7];
        #pragma unroll
        for (int n = 0; n < 7; n++) norms[n] = sqrtf(dots[n * 7 + n]);
        float edge = 0.0f, non = 0.0f;
        #pragma unroll
        for (int n = 0; n < 7; n++) {
            #pragma unroll
            for (int m = 0; m < 7; m++) {
                float cs = dots[n * 7 + m] / fmaxf(norms[n] * norms[m], 1e-8f);
                float a = c_adj[n * 7 + m];
                edge += (1.0f - cs) * a;
                float nonmask = (1.0f - a) * ((n == m) ? 0.0f : 1.0f);
                non += fmaxf(cs - 0.35f, 0.0f) * nonmask;
            }
        }
        g_phys_part[b] = edge / 41.0f + 0.5f * non / 8.0f;

        float fn = sqrtf(dots[56]);
        float al = 0.0f;
        #pragma unroll
        for (int n = 0; n < 7; n++) {
            float cs = dots[49 + n] / (fmaxf(norms[n], 1e-12f) * fmaxf(fn, 1e-12f));
            al += 1.0f - cs;
        }
        g_align_part[b] = al;
    }
}

// deterministic final reduction -> scalars
__global__ __launch_bounds__(256)
void final_reduce_kernel(float* __restrict__ out)
{
    const int tid = threadIdx.x;
    float p = 0.0f, a = 0.0f;
    for (int b = tid; b < BB; b += 256) { p += g_phys_part[b]; a += g_align_part[b]; }
    __shared__ float sp[256], sa[256];
    sp[tid] = p; sa[tid] = a;
    __syncthreads();
    for (int s = 128; s > 0; s >>= 1) {
        if (tid < s) { sp[tid] += sp[tid + s]; sa[tid] += sa[tid + s]; }
        __syncthreads();
    }
    if (tid == 0) {
        out[OFF_PHYS]  = sp[0];
        out[OFF_ALIGN] = sa[0] / (float)(BB * NN);
    }
}

// ---------------------------------------------------------------------------
extern "C" void kernel_launch(void* const* d_in, const int* in_sizes, int n_in,
                              void* d_out, int out_size)
{
    const float* nodes = (const float*)d_in[0];
    const float* Wq    = (const float*)d_in[1];
    const float* bq    = (const float*)d_in[2];
    const float* Wk    = (const float*)d_in[3];
    const float* bk    = (const float*)d_in[4];
    const float* Wv    = (const float*)d_in[5];
    const float* bv    = (const float*)d_in[6];
    const float* We1   = (const float*)d_in[7];
    const float* be1   = (const float*)d_in[8];
    const float* We2   = (const float*)d_in[9];
    const float* be2   = (const float*)d_in[10];
    const float* Wu1   = (const float*)d_in[11];
    const float* bu1   = (const float*)d_in[12];
    const float* Wu2   = (const float*)d_in[13];
    const float* bu2   = (const float*)d_in[14];
    const float* Wi1   = (const float*)d_in[15];
    const float* bi1   = (const float*)d_in[16];
    const float* Wi2   = (const float*)d_in[17];
    const float* bi2   = (const float*)d_in[18];

    float* out       = (float*)d_out;
    float* out_fused = out + OFF_FUSED;
    float* out_upd   = out + OFF_UPD;
    float* out_imp   = out + OFF_IMP;
    float* out_attn  = out + OFF_ATTN;

    float* q   = nullptr; cudaGetSymbolAddress((void**)&q,   g_q);
    float* k   = nullptr; cudaGetSymbolAddress((void**)&k,   g_k);
    float* v   = nullptr; cudaGetSymbolAddress((void**)&v,   g_v);
    float* la  = nullptr; cudaGetSymbolAddress((void**)&la,  g_la);
    float* rb  = nullptr; cudaGetSymbolAddress((void**)&rb,  g_rb);
    float* cc  = nullptr; cudaGetSymbolAddress((void**)&cc,  g_cc);
    float* cat = nullptr; cudaGetSymbolAddress((void**)&cat, g_cat);
    float* hid = nullptr; cudaGetSymbolAddress((void**)&hid, g_hid);

    static bool attr_set = false;
    if (!attr_set) {
        cudaFuncSetAttribute(gemm_tc_kernel,
                             cudaFuncAttributeMaxDynamicSharedMemorySize,
                             SMEM_GEMM_BYTES);
        attr_set = true;
    }

    dim3 blk(256);
    dim3 grid_big(DD / 128, MM / 128);   // 8 x 56
    dim3 grid_cc (DD / 128, BB / 128);   // 8 x 8
    const size_t shm = SMEM_GEMM_BYTES;

    // projections
    gemm_tc_kernel<<<grid_big, blk, shm>>>(MM, DD, DD, nodes, DD, Wq, bq, nullptr, q, 0);
    gemm_tc_kernel<<<grid_big, blk, shm>>>(MM, DD, DD, nodes, DD, Wk, bk, nullptr, k, 0);
    gemm_tc_kernel<<<grid_big, blk, shm>>>(MM, DD, DD, nodes, DD, Wv, bv, nullptr, v, 0);
    gemm_tc_kernel<<<grid_big, blk, shm>>>(MM, DD, DD, nodes, DD, We1, nullptr, nullptr, la, 0);
    gemm_tc_kernel<<<grid_big, blk, shm>>>(MM, DD, DD, nodes, DD, We1 + (size_t)DD * DD,
                                           nullptr, nullptr, rb, 0);
    gemm_tc_kernel<<<grid_cc,  blk, shm>>>(BB, DD, DD, nodes + (size_t)(NN - 1) * DD, NN * DD,
                                           We1 + (size_t)2 * DD * DD, nullptr, nullptr, cc, 0);

    // edge MLP + attention + messages
    attn_kernel<<<BB, blk>>>(be1, We2, be2, out_attn);

    // update MLP
    int nconcat = (int)(((size_t)MM * DD + 255) / 256);
    concat_nm_kernel<<<nconcat, blk>>>(nodes);
    gemm_tc_kernel<<<grid_big, blk, shm>>>(MM, DD, 2 * DD, cat, 2 * DD, Wu1, bu1, nullptr, hid, 1);
    gemm_tc_kernel<<<grid_big, blk, shm>>>(MM, DD, DD, hid, DD, Wu2, bu2, nodes, out_upd, 0);

    // importance MLP
    concat_ug_kernel<<<nconcat, blk>>>(out_upd);
    gemm_tc_kernel<<<grid_big, blk, shm>>>(MM, DD, 2 * DD, cat, 2 * DD, Wi1, bi1, nullptr, hid, 1);
    gemv_imp_kernel<<<MM, 128>>>(Wi2, bi2);
    imp_kernel<<<BB, 32>>>(out_imp);

    // fused output + losses
    fused_kernel<<<BB, blk>>>(out_imp, out_upd, out_fused);
    physalign_kernel<<<BB, blk>>>(out_upd, out_fused);
    final_reduce_kernel<<<1, blk>>>(out);
}